// round 15
// baseline (speedup 1.0000x reference)
#include <cuda_runtime.h>
#include <cstdint>

#define L 1024
#define D 64
#define NBH 64
#define OUT_ELEMS (NBH*L*D)
#define SQ 68   // padded row stride (floats) for Q/K smem

__device__ float g_inv_l[NBH * L];   // per-row 1/sum(exp(s)), qk -> pv

__device__ __forceinline__ uint32_t f2tf(float x) {
    uint32_t r; asm("cvt.rna.tf32.f32 %0, %1;" : "=r"(r) : "f"(x)); return r;
}

__device__ __forceinline__ void mma_tf32(float* c,
    uint32_t a0, uint32_t a1, uint32_t a2, uint32_t a3, uint32_t b0, uint32_t b1)
{
    asm("mma.sync.aligned.m16n8k8.row.col.f32.tf32.tf32.f32 "
        "{%0,%1,%2,%3}, {%4,%5,%6,%7}, {%8,%9}, {%0,%1,%2,%3};"
        : "+f"(c[0]), "+f"(c[1]), "+f"(c[2]), "+f"(c[3])
        : "r"(a0), "r"(a1), "r"(a2), "r"(a3), "r"(b0), "r"(b1));
}

// ---------------------------------------------------------------------------
// Kernel 1: 64-row CTA strip (64 x 1024) for 3 CTAs/SM occupancy.
// e = exp(QK^T/8 masked + bias) -> score buffer (holds exp!), and
// g_inv_l = 1 / row-sum(e).  3xTF32 split MMA, raw padded-row smem,
// in-loop hi/lo tf32 split.  8 warps: wq = wid&3 (16 rows), wk = wid>>2
// (64 of the 128 kt-tile cols).  acc[8][4] = 32 regs -> ~75 regs total.
// ---------------------------------------------------------------------------
__global__ __launch_bounds__(256, 3)
void qks_kernel(const float* __restrict__ Q, const float* __restrict__ K,
                const int* __restrict__ mask, const float* __restrict__ bias,
                float* __restrict__ score)
{
    extern __shared__ float sm[];
    float* Qs   = sm;                 // 64 x 68
    float* Ks   = sm + 64 * SQ;       // 128 x 68
    float* sred = sm + 192 * SQ;      // 2 x 64

    const int tid  = threadIdx.x;
    const int lane = tid & 31, wid = tid >> 5;
    const int wq = wid & 3, wk = wid >> 2;
    const int g = lane >> 2, t = lane & 3;
    const int qt = blockIdx.x, bh = blockIdx.y;
    const int b = bh >> 4, h = bh & 15;

    // load Q tile (64 rows, stays for whole strip)
    {
        const float4* Qg = (const float4*)(Q + ((size_t)bh * L + qt * 64) * D);
        #pragma unroll
        for (int it = 0; it < 4; it++) {
            int i = tid + it * 256; int r = i >> 4, dq = i & 15;
            ((float4*)(Qs + r * SQ))[dq] = Qg[r * 16 + dq];
        }
    }

    float l_run[2] = {0.f, 0.f};

    for (int kt = 0; kt < 8; kt++) {
        __syncthreads();
        {
            const float4* Kg = (const float4*)(K + ((size_t)bh * L + kt * 128) * D);
            #pragma unroll
            for (int it = 0; it < 8; it++) {
                int i = tid + it * 256; int r = i >> 4, dq = i & 15;
                ((float4*)(Ks + r * SQ))[dq] = Kg[r * 16 + dq];
            }
        }
        __syncthreads();

        float acc[8][4];
        #pragma unroll
        for (int nt = 0; nt < 8; nt++)
            #pragma unroll
            for (int r = 0; r < 4; r++) acc[nt][r] = 0.f;

        const float* Qw = Qs + (wq * 16) * SQ;
        const float* Kw = Ks + (wk * 64) * SQ;

        #pragma unroll
        for (int kk = 0; kk < 8; kk++) {
            uint32_t ahi[4], alo[4];
            #pragma unroll
            for (int r = 0; r < 4; r++) {
                int row = g + (r & 1) * 8;
                int col = kk * 8 + t + (r >> 1) * 4;
                float x = Qw[row * SQ + col];
                uint32_t hi = f2tf(x);
                ahi[r] = hi;
                alo[r] = f2tf(x - __uint_as_float(hi));
            }
            #pragma unroll
            for (int nt = 0; nt < 8; nt++) {
                uint32_t bhi[2], blo[2];
                #pragma unroll
                for (int r = 0; r < 2; r++) {
                    float x = Kw[(nt * 8 + g) * SQ + kk * 8 + t + r * 4];
                    uint32_t hi = f2tf(x);
                    bhi[r] = hi;
                    blo[r] = f2tf(x - __uint_as_float(hi));
                }
                mma_tf32(acc[nt], ahi[0], ahi[1], ahi[2], ahi[3], blo[0], blo[1]);
                mma_tf32(acc[nt], alo[0], alo[1], alo[2], alo[3], bhi[0], bhi[1]);
                mma_tf32(acc[nt], ahi[0], ahi[1], ahi[2], ahi[3], bhi[0], bhi[1]);
            }
        }

        // epilogue: scale, mask, bias, store e=exp(s), accumulate l
        const int q0 = qt * 64 + wq * 16;
        const int cp0 = kt * 64 + wk * 32;   // float2 col-index base
        #pragma unroll
        for (int half = 0; half < 2; half++) {
            int row = q0 + half * 8 + g;
            const int2*   mrow = (const int2*)  (mask  + ((size_t)b  * L + row) * L);
            const float2* brow = (const float2*)(bias  + ((size_t)h  * L + row) * L);
            float2*       srow = (float2*)      (score + ((size_t)bh * L + row) * L);
            float lsum = 0.f;
            #pragma unroll
            for (int nt = 0; nt < 8; nt++) {
                int cp = cp0 + nt * 4 + t;
                int2   mv = mrow[cp];
                float2 bv = brow[cp];
                float s0 = acc[nt][half * 2 + 0] * 0.125f;
                float s1 = acc[nt][half * 2 + 1] * 0.125f;
                s0 = (mv.x == 0 ? -10000.f : s0) + bv.x;
                s1 = (mv.y == 0 ? -10000.f : s1) + bv.y;
                float e0 = __expf(s0), e1 = __expf(s1);
                srow[cp] = make_float2(e0, e1);
                lsum += e0 + e1;
            }
            l_run[half] += lsum;
        }
    }

    // reduce l over the 4 t-lanes, then across the 2 wk groups
    #pragma unroll
    for (int li = 0; li < 2; li++) {
        l_run[li] += __shfl_xor_sync(0xffffffffu, l_run[li], 1);
        l_run[li] += __shfl_xor_sync(0xffffffffu, l_run[li], 2);
    }
    __syncthreads();
    if (t == 0) {
        #pragma unroll
        for (int li = 0; li < 2; li++) {
            int row = wq * 16 + li * 8 + g;
            sred[wk * 64 + row] = l_run[li];
        }
    }
    __syncthreads();
    if (tid < 64) {
        float l = sred[tid] + sred[64 + tid];
        g_inv_l[(size_t)bh * L + qt * 64 + tid] = 1.0f / l;
    }
}

// ---------------------------------------------------------------------------
// Kernel 2: O = P V with P = e * inv_l; writes normalized p over e in score.
// R13 fragment layout (no swizzle), single smem buffer, no register staging
// (e loaded just before sync, V after) -> ~80 regs, 3 CTAs/SM.
// ---------------------------------------------------------------------------
__global__ __launch_bounds__(256, 3)
void pv_kernel(const float* __restrict__ V, float* score, float* __restrict__ out)
{
    extern __shared__ uint32_t smu[];
    uint32_t* AF   = smu;                    // 8192 uints: P fragments tf32
    uint32_t* VF   = smu + 8192;             // 4096 uints: V fragments tf32
    float*    sinv = (float*)(smu + 12288);  // 128 floats

    const int tid  = threadIdx.x;
    const int lane = tid & 31, wid = tid >> 5;
    const int g = lane >> 2, t = lane & 3;
    const int qt = blockIdx.x, bh = blockIdx.y;

    const float4* Vg    = (const float4*)(V + (size_t)bh * L * D);
    float*        sbase = score + ((size_t)bh * L + qt * 128) * L;

    if (tid < 128) sinv[tid] = g_inv_l[(size_t)bh * L + qt * 128 + tid];
    __syncthreads();
    const float il = sinv[tid >> 1];

    float acc[8][4];
    #pragma unroll
    for (int nt = 0; nt < 8; nt++)
        #pragma unroll
        for (int r = 0; r < 4; r++) acc[nt][r] = 0.f;

    // per-thread constant scatter indices
    const int prow = tid >> 1;
    const int wqr = prow >> 4, gp = prow & 15, gg = gp & 7, rlo = gp >> 3;
    const int vrow = tid >> 2;
    const int vkk = vrow >> 3, ts = vrow & 7, vword = ts >> 2, vt = ts & 3;

    for (int c = 0; c < 16; c++) {
        // ---- e loads for this chunk (issued while other warps MMA(c-1)) ----
        float4 se[8];
        #pragma unroll
        for (int it = 0; it < 8; it++) {
            int qcol = (tid & 1) + it * 2;
            se[it] = *(const float4*)(sbase + (size_t)prow * L + c * 64 + qcol * 4);
        }
        __syncthreads();   // all warps done with MMA(c-1): smem reusable

        // ---- transform + store: p = e*il -> gmem + fragment smem ----
        #pragma unroll
        for (int it = 0; it < 8; it++) {
            int qcol = (tid & 1) + it * 2;
            float4 p;
            p.x = se[it].x * il; p.y = se[it].y * il;
            p.z = se[it].z * il; p.w = se[it].w * il;
            *(float4*)(sbase + (size_t)prow * L + c * 64 + qcol * 4) = p;
            int kk = qcol >> 1, r = ((qcol & 1) << 1) | rlo;
            uint32_t* dst = AF + (wqr * 8 + kk) * 128 + r;
            dst[(gg * 4 + 0) * 4] = f2tf(p.x);
            dst[(gg * 4 + 1) * 4] = f2tf(p.y);
            dst[(gg * 4 + 2) * 4] = f2tf(p.z);
            dst[(gg * 4 + 3) * 4] = f2tf(p.w);
        }
        // ---- V loads (L2-resident) + fragment scatter ----
        #pragma unroll
        for (int it = 0; it < 4; it++) {
            int qd = (tid & 3) + it * 4;
            float4 sv = Vg[(size_t)(c * 64 + vrow) * 16 + qd];
            #pragma unroll
            for (int j = 0; j < 4; j++) {
                int n = qd * 4 + j;
                int nt = n >> 3, gn = n & 7;
                VF[((vkk * 8 + nt) * 32 + gn * 4 + vt) * 2 + vword] = f2tf((&sv.x)[j]);
            }
        }
        __syncthreads();   // fragments ready

        const uint4* AF4 = (const uint4*)AF;
        const uint2* VF2 = (const uint2*)VF;
        #pragma unroll
        for (int kk = 0; kk < 8; kk++) {
            uint4 a = AF4[(wid * 8 + kk) * 32 + lane];
            #pragma unroll
            for (int nt = 0; nt < 8; nt++) {
                uint2 bb = VF2[(kk * 8 + nt) * 32 + lane];
                mma_tf32(acc[nt], a.x, a.y, a.z, a.w, bb.x, bb.y);
            }
        }
    }

    #pragma unroll
    for (int half = 0; half < 2; half++) {
        int row = qt * 128 + wid * 16 + half * 8 + g;
        float2* orow = (float2*)(out + ((size_t)bh * L + row) * D);
        #pragma unroll
        for (int nt = 0; nt < 8; nt++)
            orow[nt * 4 + t] = make_float2(acc[nt][half * 2], acc[nt][half * 2 + 1]);
    }
}

// ---------------------------------------------------------------------------
extern "C" void kernel_launch(void* const* d_in, const int* in_sizes, int n_in,
                              void* d_out, int out_size)
{
    const float* Q    = (const float*)d_in[0];
    const float* K    = (const float*)d_in[1];
    const float* V    = (const float*)d_in[2];
    const int*   mask = (const int*)  d_in[3];
    const float* bias = (const float*)d_in[4];

    float* out   = (float*)d_out;
    float* score = out + OUT_ELEMS;   // tuple order: (out, score)

    const int qk_smem = (192 * SQ + 128) * 4;     // 52736 B -> 3 CTAs/SM
    const int pv_smem = (12288 + 128) * 4;        // 49664 B -> 3 CTAs/SM
    cudaFuncSetAttribute(qks_kernel, cudaFuncAttributeMaxDynamicSharedMemorySize, qk_smem);
    cudaFuncSetAttribute(pv_kernel,  cudaFuncAttributeMaxDynamicSharedMemorySize, pv_smem);

    qks_kernel<<<dim3(16, 64), 256, qk_smem>>>(Q, K, mask, bias, score);
    pv_kernel <<<dim3(8, 64), 256, pv_smem>>>(V, score, out);
}